// round 3
// baseline (speedup 1.0000x reference)
#include <cuda_runtime.h>
#include <math.h>

#define HASH_MASK ((1u << 19) - 1u)
#define P2 2654435761u
#define P3 805459861u

#define NTHREADS 768
#define TILE_PTS 768
#define STAGE_STRIDE 34   // floats per point in staging (32 + 2 pad -> conflict-free)

struct Res16 { int r[16]; };

__global__ __launch_bounds__(NTHREADS, 1)
void hashenc_kernel(const float* __restrict__ pos,
                    const float2* __restrict__ tab,
                    float2* __restrict__ out,
                    Res16 rp, int n, int ntiles, int cacheEntries)
{
    extern __shared__ float2 smem[];
    float2* cache = smem;                         // levels 0..1, linear grid index
    float*  stage = (float*)(smem + cacheEntries);// TILE_PTS * STAGE_STRIDE floats

    const int t = threadIdx.x;
    const int r0 = rp.r[0], r1 = rp.r[1];
    const int c0 = r0 * r0 * r0;

    // ---- fill coarse-level caches (scattered gather -> linear smem) ----
    for (int e = t; e < cacheEntries; e += NTHREADS) {
        int res, idx;
        if (e < c0) { res = r0; idx = e; }
        else        { res = r1; idx = e - c0; }
        int z = idx % res;
        int y = (idx / res) % res;
        int x = idx / (res * res);
        unsigned h = ((unsigned)x ^ (unsigned)y * P2 ^ (unsigned)z * P3) & HASH_MASK;
        cache[e] = __ldg(&tab[h]);
    }
    __syncthreads();

    const int nf2 = n * 16;   // total float2 outputs

    for (int tile = blockIdx.x; tile < ntiles; tile += gridDim.x) {
        const int i = tile * TILE_PTS + t;   // this thread's point

        if (i < n) {
            float px = (pos[3 * i + 0] + 1.0f) * 0.5f;
            float py = (pos[3 * i + 1] + 1.0f) * 0.5f;
            float pz = (pos[3 * i + 2] + 1.0f) * 0.5f;
            float* my = stage + t * STAGE_STRIDE;

            // ---- levels 0,1 from shared-memory cache ----
            #pragma unroll
            for (int l = 0; l < 2; ++l) {
                const int r  = (l == 0) ? r0 : r1;
                const int rm = r - 1;
                const int base = (l == 0) ? 0 : c0;
                const float rmf = (float)rm;

                float sx = px * rmf, sy = py * rmf, sz = pz * rmf;
                float fx = floorf(sx), fy = floorf(sy), fz = floorf(sz);
                float wx = sx - fx, wy = sy - fy, wz = sz - fz;
                int gx = (int)fx, gy = (int)fy, gz = (int)fz;
                int x0 = min(max(gx, 0), rm), x1 = min(gx + 1, rm);
                int y0 = min(max(gy, 0), rm), y1 = min(gy + 1, rm);
                int z0 = min(max(gz, 0), rm), z1 = min(gz + 1, rm);

                int bx0 = base + x0 * r * r, bx1 = base + x1 * r * r;
                int oy0 = y0 * r, oy1 = y1 * r;

                float2 f000 = cache[bx0 + oy0 + z0];
                float2 f001 = cache[bx0 + oy0 + z1];
                float2 f010 = cache[bx0 + oy1 + z0];
                float2 f011 = cache[bx0 + oy1 + z1];
                float2 f100 = cache[bx1 + oy0 + z0];
                float2 f101 = cache[bx1 + oy0 + z1];
                float2 f110 = cache[bx1 + oy1 + z0];
                float2 f111 = cache[bx1 + oy1 + z1];

                float ux = 1.0f - wx, uy = 1.0f - wy, uz = 1.0f - wz;
                float ax = 0.0f, ay = 0.0f;
                float w;
                w = ux*uy*uz; ax = fmaf(w, f000.x, ax); ay = fmaf(w, f000.y, ay);
                w = ux*uy*wz; ax = fmaf(w, f001.x, ax); ay = fmaf(w, f001.y, ay);
                w = ux*wy*uz; ax = fmaf(w, f010.x, ax); ay = fmaf(w, f010.y, ay);
                w = ux*wy*wz; ax = fmaf(w, f011.x, ax); ay = fmaf(w, f011.y, ay);
                w = wx*uy*uz; ax = fmaf(w, f100.x, ax); ay = fmaf(w, f100.y, ay);
                w = wx*uy*wz; ax = fmaf(w, f101.x, ax); ay = fmaf(w, f101.y, ay);
                w = wx*wy*uz; ax = fmaf(w, f110.x, ax); ay = fmaf(w, f110.y, ay);
                w = wx*wy*wz; ax = fmaf(w, f111.x, ax); ay = fmaf(w, f111.y, ay);
                my[2*l]   = ax;
                my[2*l+1] = ay;
            }

            // ---- levels 2..15 via global gathers ----
            #pragma unroll
            for (int l = 2; l < 16; ++l) {
                const int rm = rp.r[l] - 1;
                const float rmf = (float)rm;

                float sx = px * rmf, sy = py * rmf, sz = pz * rmf;
                float fx = floorf(sx), fy = floorf(sy), fz = floorf(sz);
                float wx = sx - fx, wy = sy - fy, wz = sz - fz;
                int gx = (int)fx, gy = (int)fy, gz = (int)fz;
                int x0 = min(max(gx, 0), rm), x1 = min(gx + 1, rm);
                int y0 = min(max(gy, 0), rm), y1 = min(gy + 1, rm);
                int z0 = min(max(gz, 0), rm), z1 = min(gz + 1, rm);

                unsigned hx0 = (unsigned)x0, hx1 = (unsigned)x1;
                unsigned hy0 = (unsigned)y0 * P2, hy1 = (unsigned)y1 * P2;
                unsigned hz0 = (unsigned)z0 * P3, hz1 = (unsigned)z1 * P3;

                float2 f000 = __ldg(&tab[(hx0 ^ hy0 ^ hz0) & HASH_MASK]);
                float2 f001 = __ldg(&tab[(hx0 ^ hy0 ^ hz1) & HASH_MASK]);
                float2 f010 = __ldg(&tab[(hx0 ^ hy1 ^ hz0) & HASH_MASK]);
                float2 f011 = __ldg(&tab[(hx0 ^ hy1 ^ hz1) & HASH_MASK]);
                float2 f100 = __ldg(&tab[(hx1 ^ hy0 ^ hz0) & HASH_MASK]);
                float2 f101 = __ldg(&tab[(hx1 ^ hy0 ^ hz1) & HASH_MASK]);
                float2 f110 = __ldg(&tab[(hx1 ^ hy1 ^ hz0) & HASH_MASK]);
                float2 f111 = __ldg(&tab[(hx1 ^ hy1 ^ hz1) & HASH_MASK]);

                float ux = 1.0f - wx, uy = 1.0f - wy, uz = 1.0f - wz;
                float ax = 0.0f, ay = 0.0f;
                float w;
                w = ux*uy*uz; ax = fmaf(w, f000.x, ax); ay = fmaf(w, f000.y, ay);
                w = ux*uy*wz; ax = fmaf(w, f001.x, ax); ay = fmaf(w, f001.y, ay);
                w = ux*wy*uz; ax = fmaf(w, f010.x, ax); ay = fmaf(w, f010.y, ay);
                w = ux*wy*wz; ax = fmaf(w, f011.x, ax); ay = fmaf(w, f011.y, ay);
                w = wx*uy*uz; ax = fmaf(w, f100.x, ax); ay = fmaf(w, f100.y, ay);
                w = wx*uy*wz; ax = fmaf(w, f101.x, ax); ay = fmaf(w, f101.y, ay);
                w = wx*wy*uz; ax = fmaf(w, f110.x, ax); ay = fmaf(w, f110.y, ay);
                w = wx*wy*wz; ax = fmaf(w, f111.x, ax); ay = fmaf(w, f111.y, ay);
                my[2*l]   = ax;
                my[2*l+1] = ay;
            }
        }
        __syncthreads();

        // ---- coalesced write: tile covers TILE_PTS*16 float2 contiguous ----
        const long tilebase = (long)tile * (TILE_PTS * 16);
        const float2* stage2 = (const float2*)stage;
        #pragma unroll
        for (int k = 0; k < 16; ++k) {
            int idx = k * TILE_PTS + t;
            long g = tilebase + idx;
            if (g < nf2) {
                int p = idx >> 4;
                int c = idx & 15;
                out[g] = stage2[p * (STAGE_STRIDE / 2) + c];
            }
        }
        __syncthreads();   // protect stage reuse next tile
    }
}

extern "C" void kernel_launch(void* const* d_in, const int* in_sizes, int n_in,
                              void* d_out, int out_size)
{
    const float*  pos = (const float*)d_in[0];
    const float2* tab = (const float2*)d_in[1];
    float2*       out = (float2*)d_out;

    const int n = in_sizes[0] / 3;

    // Mirror numpy: growth = exp((log(2048)-log(16))/15); res_l = min(int(16*growth**l), 2048)
    Res16 rp;
    const double growth = exp((log(2048.0) - log(16.0)) / 15.0);
    for (int l = 0; l < 16; ++l) {
        double v = 16.0 * pow(growth, (double)l);
        int r = (int)v;
        rp.r[l] = r > 2048 ? 2048 : r;
    }

    const int cacheEntries = rp.r[0]*rp.r[0]*rp.r[0] + rp.r[1]*rp.r[1]*rp.r[1]; // 14744
    const int smemBytes = cacheEntries * (int)sizeof(float2)
                        + TILE_PTS * STAGE_STRIDE * (int)sizeof(float);          // 117952 + 104448

    cudaFuncSetAttribute(hashenc_kernel,
                         cudaFuncAttributeMaxDynamicSharedMemorySize, smemBytes);

    const int ntiles = (n + TILE_PTS - 1) / TILE_PTS;
    const int grid = 148;
    hashenc_kernel<<<grid, NTHREADS, smemBytes>>>(pos, tab, out, rp, n, ntiles, cacheEntries);
}

// round 4
// speedup vs baseline: 2.6034x; 2.6034x over previous
#include <cuda_runtime.h>
#include <math.h>

#define HASH_MASK ((1u << 19) - 1u)
#define P2 2654435761u
#define P3 805459861u

#define NP (1 << 20)
#define NCELLS 32768            // 32^3 Morton cells

struct Res16 { int r[16]; };

__device__ float4   g_sorted[NP];       // xyz + orig-index (bitcast)
__device__ unsigned g_hist[NCELLS];
__device__ unsigned g_off[NCELLS];

__device__ __forceinline__ unsigned expand5(unsigned v) {
    // 5 bits -> every 3rd bit position
    return (v & 1u) | ((v & 2u) << 2) | ((v & 4u) << 4)
         | ((v & 8u) << 6) | ((v & 16u) << 8);
}

__device__ __forceinline__ unsigned cell_of(float x, float y, float z) {
    float px = (x + 1.0f) * 0.5f;
    float py = (y + 1.0f) * 0.5f;
    float pz = (z + 1.0f) * 0.5f;
    int cx = min(max((int)(px * 32.0f), 0), 31);
    int cy = min(max((int)(py * 32.0f), 0), 31);
    int cz = min(max((int)(pz * 32.0f), 0), 31);
    return expand5((unsigned)cx) | (expand5((unsigned)cy) << 1) | (expand5((unsigned)cz) << 2);
}

__global__ void zero_hist_kernel() {
    int i = blockIdx.x * blockDim.x + threadIdx.x;
    if (i < NCELLS) g_hist[i] = 0u;
}

__global__ void hist_kernel(const float* __restrict__ pos, int n) {
    int i = blockIdx.x * blockDim.x + threadIdx.x;
    if (i >= n) return;
    unsigned c = cell_of(pos[3*i], pos[3*i+1], pos[3*i+2]);
    atomicAdd(&g_hist[c], 1u);
}

__global__ __launch_bounds__(1024)
void scan_kernel() {
    __shared__ unsigned s[1024];
    const int t = threadIdx.x;
    const int base = t * (NCELLS / 1024);   // 32 bins per thread

    unsigned total = 0;
    #pragma unroll
    for (int k = 0; k < NCELLS / 1024; ++k) total += g_hist[base + k];
    s[t] = total;
    __syncthreads();

    // inclusive Hillis-Steele scan over 1024 partials
    for (int d = 1; d < 1024; d <<= 1) {
        unsigned v = (t >= d) ? s[t - d] : 0u;
        __syncthreads();
        s[t] += v;
        __syncthreads();
    }
    unsigned blockExcl = s[t] - total;

    unsigned run = blockExcl;
    #pragma unroll
    for (int k = 0; k < NCELLS / 1024; ++k) {
        unsigned h = g_hist[base + k];
        g_off[base + k] = run;
        run += h;
    }
}

__global__ void scatter_kernel(const float* __restrict__ pos, int n) {
    int i = blockIdx.x * blockDim.x + threadIdx.x;
    if (i >= n) return;
    float x = pos[3*i], y = pos[3*i+1], z = pos[3*i+2];
    unsigned c = cell_of(x, y, z);
    unsigned dst = atomicAdd(&g_off[c], 1u);
    g_sorted[dst] = make_float4(x, y, z, __uint_as_float((unsigned)i));
}

__global__ __launch_bounds__(256)
void encode_kernel(const float2* __restrict__ tab,
                   float4* __restrict__ out4,
                   Res16 rp, int n)
{
    int j = blockIdx.x * blockDim.x + threadIdx.x;
    if (j >= n) return;

    float4 s = g_sorted[j];
    unsigned orig = __float_as_uint(s.w);
    float px = (s.x + 1.0f) * 0.5f;
    float py = (s.y + 1.0f) * 0.5f;
    float pz = (s.z + 1.0f) * 0.5f;

    #pragma unroll
    for (int l = 0; l < 16; l += 2) {
        float res2[4];
        #pragma unroll
        for (int h = 0; h < 2; ++h) {
            const int rm = rp.r[l + h] - 1;
            const float rmf = (float)rm;

            float sx = px * rmf, sy = py * rmf, sz = pz * rmf;
            float fx = floorf(sx), fy = floorf(sy), fz = floorf(sz);
            float wx = sx - fx, wy = sy - fy, wz = sz - fz;
            int gx = (int)fx, gy = (int)fy, gz = (int)fz;
            int x0 = min(gx, rm),     x1 = min(gx + 1, rm);
            int y0 = min(gy, rm),     y1 = min(gy + 1, rm);
            int z0 = min(gz, rm),     z1 = min(gz + 1, rm);

            unsigned hx0 = (unsigned)x0,      hx1 = (unsigned)x1;
            unsigned hy0 = (unsigned)y0 * P2, hy1 = (unsigned)y1 * P2;
            unsigned hz0 = (unsigned)z0 * P3, hz1 = (unsigned)z1 * P3;

            float2 f000 = __ldg(&tab[(hx0 ^ hy0 ^ hz0) & HASH_MASK]);
            float2 f001 = __ldg(&tab[(hx0 ^ hy0 ^ hz1) & HASH_MASK]);
            float2 f010 = __ldg(&tab[(hx0 ^ hy1 ^ hz0) & HASH_MASK]);
            float2 f011 = __ldg(&tab[(hx0 ^ hy1 ^ hz1) & HASH_MASK]);
            float2 f100 = __ldg(&tab[(hx1 ^ hy0 ^ hz0) & HASH_MASK]);
            float2 f101 = __ldg(&tab[(hx1 ^ hy0 ^ hz1) & HASH_MASK]);
            float2 f110 = __ldg(&tab[(hx1 ^ hy1 ^ hz0) & HASH_MASK]);
            float2 f111 = __ldg(&tab[(hx1 ^ hy1 ^ hz1) & HASH_MASK]);

            float ux = 1.0f - wx, uy = 1.0f - wy, uz = 1.0f - wz;
            float ax = 0.0f, ay = 0.0f, w;
            w = ux*uy*uz; ax = fmaf(w, f000.x, ax); ay = fmaf(w, f000.y, ay);
            w = ux*uy*wz; ax = fmaf(w, f001.x, ax); ay = fmaf(w, f001.y, ay);
            w = ux*wy*uz; ax = fmaf(w, f010.x, ax); ay = fmaf(w, f010.y, ay);
            w = ux*wy*wz; ax = fmaf(w, f011.x, ax); ay = fmaf(w, f011.y, ay);
            w = wx*uy*uz; ax = fmaf(w, f100.x, ax); ay = fmaf(w, f100.y, ay);
            w = wx*uy*wz; ax = fmaf(w, f101.x, ax); ay = fmaf(w, f101.y, ay);
            w = wx*wy*uz; ax = fmaf(w, f110.x, ax); ay = fmaf(w, f110.y, ay);
            w = wx*wy*wz; ax = fmaf(w, f111.x, ax); ay = fmaf(w, f111.y, ay);
            res2[2*h]   = ax;
            res2[2*h+1] = ay;
        }
        out4[(size_t)orig * 8 + (l >> 1)] = make_float4(res2[0], res2[1], res2[2], res2[3]);
    }
}

extern "C" void kernel_launch(void* const* d_in, const int* in_sizes, int n_in,
                              void* d_out, int out_size)
{
    const float*  pos = (const float*)d_in[0];
    const float2* tab = (const float2*)d_in[1];
    float4*       out4 = (float4*)d_out;

    const int n = in_sizes[0] / 3;

    Res16 rp;
    const double growth = exp((log(2048.0) - log(16.0)) / 15.0);
    for (int l = 0; l < 16; ++l) {
        double v = 16.0 * pow(growth, (double)l);
        int r = (int)v;
        rp.r[l] = r > 2048 ? 2048 : r;
    }

    const int T = 256;
    zero_hist_kernel<<<(NCELLS + T - 1) / T, T>>>();
    hist_kernel<<<(n + T - 1) / T, T>>>(pos, n);
    scan_kernel<<<1, 1024>>>();
    scatter_kernel<<<(n + T - 1) / T, T>>>(pos, n);
    encode_kernel<<<(n + T - 1) / T, T>>>(tab, out4, rp, n);
}